// round 8
// baseline (speedup 1.0000x reference)
#include <cuda_runtime.h>

// out = x^2 * 0.1 over N fp32. HBM-bound streaming kernel.
// float4, 4-deep explicit load batching (MLP to cover 577-cyc DRAM latency),
// streaming cache hints (.cs) since the 512MB working set has zero reuse.

__global__ void __launch_bounds__(256) poly_kernel_v4u4(const float4* __restrict__ x,
                                                        float4* __restrict__ out,
                                                        int n4) {
    const int stride = gridDim.x * blockDim.x;
    int i = blockIdx.x * blockDim.x + threadIdx.x;

    // Main unrolled loop: 4 independent 128-bit streaming loads issued up front.
    for (; i + 3 * stride < n4; i += 4 * stride) {
        float4 v0 = __ldcs(&x[i]);
        float4 v1 = __ldcs(&x[i + stride]);
        float4 v2 = __ldcs(&x[i + 2 * stride]);
        float4 v3 = __ldcs(&x[i + 3 * stride]);

        float4 r0, r1, r2, r3;
        r0.x = v0.x * v0.x * 0.1f; r0.y = v0.y * v0.y * 0.1f;
        r0.z = v0.z * v0.z * 0.1f; r0.w = v0.w * v0.w * 0.1f;
        r1.x = v1.x * v1.x * 0.1f; r1.y = v1.y * v1.y * 0.1f;
        r1.z = v1.z * v1.z * 0.1f; r1.w = v1.w * v1.w * 0.1f;
        r2.x = v2.x * v2.x * 0.1f; r2.y = v2.y * v2.y * 0.1f;
        r2.z = v2.z * v2.z * 0.1f; r2.w = v2.w * v2.w * 0.1f;
        r3.x = v3.x * v3.x * 0.1f; r3.y = v3.y * v3.y * 0.1f;
        r3.z = v3.z * v3.z * 0.1f; r3.w = v3.w * v3.w * 0.1f;

        __stcs(&out[i],              r0);
        __stcs(&out[i + stride],     r1);
        __stcs(&out[i + 2 * stride], r2);
        __stcs(&out[i + 3 * stride], r3);
    }

    // Remainder (at most 3 iterations per thread).
    for (; i < n4; i += stride) {
        float4 v = __ldcs(&x[i]);
        float4 r;
        r.x = v.x * v.x * 0.1f;
        r.y = v.y * v.y * 0.1f;
        r.z = v.z * v.z * 0.1f;
        r.w = v.w * v.w * 0.1f;
        __stcs(&out[i], r);
    }
}

// Scalar tail for n % 4 != 0 (not hit for 64*1024*1024, but safe).
__global__ void poly_kernel_tail(const float* __restrict__ x,
                                 float* __restrict__ out,
                                 int start, int n) {
    int i = start + blockIdx.x * blockDim.x + threadIdx.x;
    if (i < n) {
        float v = x[i];
        out[i] = v * v * 0.1f;
    }
}

extern "C" void kernel_launch(void* const* d_in, const int* in_sizes, int n_in,
                              void* d_out, int out_size) {
    const float* x = (const float*)d_in[0];
    float* out = (float*)d_out;
    int n = in_sizes[0];

    int n4 = n / 4;
    const int threads = 256;
    int blocks = (n4 + threads - 1) / threads;
    const int max_blocks = 148 * 16;  // ~7 unrolled macro-iters per thread
    if (blocks > max_blocks) blocks = max_blocks;

    if (n4 > 0) {
        poly_kernel_v4u4<<<blocks, threads>>>((const float4*)x, (float4*)out, n4);
    }

    int rem = n - n4 * 4;
    if (rem > 0) {
        poly_kernel_tail<<<1, 256>>>(x, out, n4 * 4, n);
    }
}

// round 9
// speedup vs baseline: 1.0397x; 1.0397x over previous
#include <cuda_runtime.h>

// out = x^2 * 0.1 over N fp32. HBM-bound streaming kernel.
// One float4 per thread, exact-fit grid, NO loop: keeps MLP_p1 = 1 so
// cross-CTA L1tex-queue spread stays at its 1.10 floor (B300 spread model:
// spr = 1.10 + 25*(oe*MLP_p1 - 16)/T_CTA; batched loads regressed in R8).

__global__ void __launch_bounds__(256) poly_kernel_flat(const float4* __restrict__ x,
                                                        float4* __restrict__ out,
                                                        int n4) {
    int i = blockIdx.x * 256 + threadIdx.x;
    if (i < n4) {
        float4 v = x[i];
        float4 r;
        r.x = v.x * v.x * 0.1f;
        r.y = v.y * v.y * 0.1f;
        r.z = v.z * v.z * 0.1f;
        r.w = v.w * v.w * 0.1f;
        out[i] = r;
    }
}

// Scalar tail for n % 4 != 0 (not hit for 64*1024*1024, but safe).
__global__ void poly_kernel_tail(const float* __restrict__ x,
                                 float* __restrict__ out,
                                 int start, int n) {
    int i = start + blockIdx.x * blockDim.x + threadIdx.x;
    if (i < n) {
        float v = x[i];
        out[i] = v * v * 0.1f;
    }
}

extern "C" void kernel_launch(void* const* d_in, const int* in_sizes, int n_in,
                              void* d_out, int out_size) {
    const float* x = (const float*)d_in[0];
    float* out = (float*)d_out;
    int n = in_sizes[0];

    int n4 = n / 4;
    if (n4 > 0) {
        int blocks = (n4 + 255) / 256;  // exact fit: one float4 per thread
        poly_kernel_flat<<<blocks, 256>>>((const float4*)x, (float4*)out, n4);
    }

    int rem = n - n4 * 4;
    if (rem > 0) {
        poly_kernel_tail<<<1, 256>>>(x, out, n4 * 4, n);
    }
}